// round 2
// baseline (speedup 1.0000x reference)
#include <cuda_runtime.h>
#include <cuda_bf16.h>
#include <math.h>

#define NN 100000
#define NE 800000
#define NG 16
#define NF 128
#define NH 128
#define NC 2

// ---------------- persistent scratch (alloc-free rule: __device__ globals) ---
__device__ int   g_deg[NN];          // in-degree from edges (excl. self loop)
__device__ float g_dinv[NN];         // 1/sqrt(deg+1)
__device__ int   g_ptr[NN + 1];      // CSR row pointers (by destination)
__device__ int   g_fill[NN];         // fill cursors
__device__ int   g_srcs[NE];         // source node per CSR slot
__device__ float g_nrm[NE];          // edge norm per CSR slot
__device__ float g_h1[(size_t)NN * NF];   // x @ W1
__device__ float g_act[(size_t)NN * NH];  // relu(agg1 + b1)
__device__ float g_h2[NN * NC];           // act @ W2
__device__ float g_sums[NG * NC];
__device__ float g_cnts[NG];
__device__ int   g_bsum[32];         // scan spine

// ---------------- init / reset --------------------------------------------
__global__ void k_reset() {
    int i = blockIdx.x * blockDim.x + threadIdx.x;
    if (i < NN) { g_deg[i] = 0; g_fill[i] = 0; }
    if (i < NG * NC) g_sums[i] = 0.f;
    if (i < NG) g_cnts[i] = 0.f;
}

// ---------------- degree histogram (int atomics, cheap) -------------------
// NOTE: edge_index is int32 on the wire (JAX x64 disabled downcasts int64).
__global__ void k_hist(const int* __restrict__ ei) {
    int e = blockIdx.x * blockDim.x + threadIdx.x;
    if (e >= NE) return;
    int c = ei[NE + e];                // col = target
    atomicAdd(&g_deg[c], 1);
}

__global__ void k_dinv() {
    int i = blockIdx.x * blockDim.x + threadIdx.x;
    if (i >= NN) return;
    g_dinv[i] = rsqrtf((float)(g_deg[i] + 1));  // +1 self loop; always > 0
}

// ---------------- exclusive scan over g_deg -> g_ptr ----------------------
// 25 blocks x 1024 threads x 4 elems = 102400 >= NN
__global__ void k_scanA() {
    __shared__ int sh[1024];
    int b = blockIdx.x, t = threadIdx.x;
    int base = b * 4096 + t * 4;
    int v[4]; int s = 0;
#pragma unroll
    for (int j = 0; j < 4; ++j) {
        v[j] = (base + j < NN) ? g_deg[base + j] : 0;
        s += v[j];
    }
    sh[t] = s; __syncthreads();
    for (int off = 1; off < 1024; off <<= 1) {
        int x = (t >= off) ? sh[t - off] : 0;
        __syncthreads();
        sh[t] += x;
        __syncthreads();
    }
    int excl = sh[t] - s;
    if (t == 1023) g_bsum[b] = sh[1023];
    int run = excl;
#pragma unroll
    for (int j = 0; j < 4; ++j) {
        if (base + j < NN) g_ptr[base + j] = run;
        run += v[j];
    }
}

__global__ void k_scanSpine() {
    if (threadIdx.x == 0) {
        int acc = 0;
        for (int b = 0; b < 25; ++b) { int x = g_bsum[b]; g_bsum[b] = acc; acc += x; }
        g_ptr[NN] = acc;   // == NE
    }
}

__global__ void k_scanAdd() {
    int i = blockIdx.x * blockDim.x + threadIdx.x;
    if (i < NN) g_ptr[i] += g_bsum[i / 4096];
}

// ---------------- CSR fill (by destination) -------------------------------
__global__ void k_fill(const int* __restrict__ ei) {
    int e = blockIdx.x * blockDim.x + threadIdx.x;
    if (e >= NE) return;
    int r = ei[e];
    int c = ei[NE + e];
    int pos = g_ptr[c] + atomicAdd(&g_fill[c], 1);
    g_srcs[pos] = r;
    g_nrm[pos]  = g_dinv[r] * g_dinv[c];
}

// ---------------- GEMM1: g_h1 = X @ W1  (fp32, 128x128x8 tiles) -----------
__global__ __launch_bounds__(256) void k_gemm1(const float* __restrict__ X,
                                               const float* __restrict__ W) {
    __shared__ float As[8][128];
    __shared__ float Bs[8][128];
    int bm = blockIdx.x * 128;
    int tid = threadIdx.x;
    int tx = tid & 15, ty = tid >> 4;         // 16 x 16 thread grid
    float acc[8][8];
#pragma unroll
    for (int i = 0; i < 8; ++i)
#pragma unroll
        for (int j = 0; j < 8; ++j) acc[i][j] = 0.f;

    int ar = tid >> 1, ac = (tid & 1) * 4;    // A load: 128 rows x 8 cols
    int br = tid >> 5, bc = (tid & 31) * 4;   // B load: 8 rows x 128 cols
    int gr = bm + ar;

    for (int k0 = 0; k0 < 128; k0 += 8) {
        float4 av = (gr < NN) ? *(const float4*)(X + (size_t)gr * 128 + k0 + ac)
                              : make_float4(0.f, 0.f, 0.f, 0.f);
        As[ac + 0][ar] = av.x; As[ac + 1][ar] = av.y;
        As[ac + 2][ar] = av.z; As[ac + 3][ar] = av.w;
        *(float4*)&Bs[br][bc] = *(const float4*)(W + (size_t)(k0 + br) * 128 + bc);
        __syncthreads();
#pragma unroll
        for (int k = 0; k < 8; ++k) {
            float ra[8], rb[8];
            *(float4*)&ra[0] = *(const float4*)&As[k][ty * 8];
            *(float4*)&ra[4] = *(const float4*)&As[k][ty * 8 + 4];
            *(float4*)&rb[0] = *(const float4*)&Bs[k][tx * 8];
            *(float4*)&rb[4] = *(const float4*)&Bs[k][tx * 8 + 4];
#pragma unroll
            for (int i = 0; i < 8; ++i)
#pragma unroll
                for (int j = 0; j < 8; ++j) acc[i][j] += ra[i] * rb[j];
        }
        __syncthreads();
    }
#pragma unroll
    for (int i = 0; i < 8; ++i) {
        int row = bm + ty * 8 + i;
        if (row < NN) {
            float* o = g_h1 + (size_t)row * 128 + tx * 8;
            *(float4*)(o + 0) = *(float4*)&acc[i][0];
            *(float4*)(o + 4) = *(float4*)&acc[i][4];
        }
    }
}

// ---------------- layer-1 aggregation: warp per node, CSR gather ----------
__global__ void k_agg1(const float* __restrict__ b1) {
    int warp = (blockIdx.x * blockDim.x + threadIdx.x) >> 5;
    int lane = threadIdx.x & 31;
    if (warp >= NN) return;
    int p0 = g_ptr[warp], p1 = g_ptr[warp + 1];
    float d = g_dinv[warp];
    const float4* hs = (const float4*)(g_h1 + (size_t)warp * 128);
    float4 v = hs[lane];
    float w0 = d * d;
    float4 acc = make_float4(w0 * v.x, w0 * v.y, w0 * v.z, w0 * v.w);
    for (int e = p0; e < p1; ++e) {
        int r = g_srcs[e];
        float w = g_nrm[e];
        const float4* hr = (const float4*)(g_h1 + (size_t)r * 128);
        float4 u = hr[lane];
        acc.x += w * u.x; acc.y += w * u.y; acc.z += w * u.z; acc.w += w * u.w;
    }
    float4 bb = ((const float4*)b1)[lane];
    acc.x = fmaxf(acc.x + bb.x, 0.f);
    acc.y = fmaxf(acc.y + bb.y, 0.f);
    acc.z = fmaxf(acc.z + bb.z, 0.f);
    acc.w = fmaxf(acc.w + bb.w, 0.f);
    ((float4*)(g_act + (size_t)warp * 128))[lane] = acc;
}

// ---------------- skinny GEMM2: h2 = act @ W2  (warp per node) ------------
__global__ void k_h2(const float* __restrict__ W2) {
    int warp = (blockIdx.x * blockDim.x + threadIdx.x) >> 5;
    int lane = threadIdx.x & 31;
    if (warp >= NN) return;
    float4 v = ((const float4*)(g_act + (size_t)warp * 128))[lane];
    int k = lane * 4;
    float s0 = v.x * W2[(k + 0) * 2 + 0] + v.y * W2[(k + 1) * 2 + 0]
             + v.z * W2[(k + 2) * 2 + 0] + v.w * W2[(k + 3) * 2 + 0];
    float s1 = v.x * W2[(k + 0) * 2 + 1] + v.y * W2[(k + 1) * 2 + 1]
             + v.z * W2[(k + 2) * 2 + 1] + v.w * W2[(k + 3) * 2 + 1];
#pragma unroll
    for (int off = 16; off > 0; off >>= 1) {
        s0 += __shfl_xor_sync(0xffffffffu, s0, off);
        s1 += __shfl_xor_sync(0xffffffffu, s1, off);
    }
    if (lane == 0) {
        g_h2[warp * 2 + 0] = s0;
        g_h2[warp * 2 + 1] = s1;
    }
}

// ---------------- layer-2 aggregation + mean-pool partial -----------------
__global__ void k_agg2pool(const float* __restrict__ b2,
                           const int* __restrict__ batch) {
    __shared__ float s_sums[NG * NC];
    __shared__ float s_cnt[NG];
    int t = threadIdx.x;
    if (t < NG * NC) s_sums[t] = 0.f;
    if (t < NG) s_cnt[t] = 0.f;
    __syncthreads();

    int i = blockIdx.x * blockDim.x + t;
    if (i < NN) {
        float d = g_dinv[i];
        float a0 = d * d * g_h2[i * 2 + 0];
        float a1 = d * d * g_h2[i * 2 + 1];
        int p0 = g_ptr[i], p1 = g_ptr[i + 1];
        for (int e = p0; e < p1; ++e) {
            int r = g_srcs[e];
            float w = g_nrm[e];
            a0 += w * g_h2[r * 2 + 0];
            a1 += w * g_h2[r * 2 + 1];
        }
        a0 += b2[0]; a1 += b2[1];
        int g = batch[i];
        atomicAdd(&s_sums[g * 2 + 0], a0);
        atomicAdd(&s_sums[g * 2 + 1], a1);
        atomicAdd(&s_cnt[g], 1.f);
    }
    __syncthreads();
    if (t < NG * NC) atomicAdd(&g_sums[t], s_sums[t]);
    if (t < NG) atomicAdd(&g_cnts[t], s_cnt[t]);
}

// ---------------- final: mean + log_softmax -------------------------------
__global__ void k_final(float* __restrict__ out) {
    int t = threadIdx.x;
    if (t >= NG) return;
    float c = fmaxf(g_cnts[t], 1.f);
    float p0 = g_sums[t * 2 + 0] / c;
    float p1 = g_sums[t * 2 + 1] / c;
    float m = fmaxf(p0, p1);
    float l = m + logf(expf(p0 - m) + expf(p1 - m));
    out[t * 2 + 0] = p0 - l;
    out[t * 2 + 1] = p1 - l;
}

// ---------------- launch --------------------------------------------------
extern "C" void kernel_launch(void* const* d_in, const int* in_sizes, int n_in,
                              void* d_out, int out_size) {
    const float* x     = (const float*)d_in[0];
    const int*   ei    = (const int*)d_in[1];     // int32! (JAX x64 disabled)
    const int*   batch = (const int*)d_in[2];     // int32!
    const float* W1    = (const float*)d_in[3];
    const float* b1    = (const float*)d_in[4];
    const float* W2    = (const float*)d_in[5];
    const float* b2    = (const float*)d_in[6];
    float* out = (float*)d_out;

    k_reset<<<(NN + 255) / 256, 256>>>();
    k_hist<<<(NE + 255) / 256, 256>>>(ei);
    k_dinv<<<(NN + 255) / 256, 256>>>();
    k_scanA<<<25, 1024>>>();
    k_scanSpine<<<1, 32>>>();
    k_scanAdd<<<(NN + 255) / 256, 256>>>();
    k_fill<<<(NE + 255) / 256, 256>>>(ei);
    k_gemm1<<<(NN + 127) / 128, 256>>>(x, W1);
    k_agg1<<<(NN * 32 + 255) / 256, 256>>>(b1);
    k_h2<<<(NN * 32 + 255) / 256, 256>>>(W2);
    k_agg2pool<<<(NN + 255) / 256, 256>>>(b2, batch);
    k_final<<<1, 32>>>(out);
}

// round 3
// speedup vs baseline: 1.0117x; 1.0117x over previous
#include <cuda_runtime.h>
#include <cuda_bf16.h>
#include <math.h>

#define NN 100000
#define NE 800000
#define NG 16
#define NF 128
#define NH 128
#define NC 2

typedef unsigned long long ull;

// ---------------- persistent scratch (alloc-free rule: __device__ globals) ---
__device__ int   g_deg[NN];
__device__ float g_dinv[NN];
__device__ int   g_ptr[NN + 1];
__device__ int   g_fill[NN];
__device__ int   g_srcs[NE];
__device__ float g_nrm[NE];
__device__ float g_h1[(size_t)NN * NF];   // x @ W1
__device__ float g_h2[NN * NC];           // relu(agg1+b1) @ W2  (fused)
__device__ float g_sums[NG * NC];
__device__ float g_cnts[NG];
__device__ int   g_bsum[32];

// ---------------- f32x2 helpers -------------------------------------------
__device__ __forceinline__ void ffma2(ull& d, ull a, ull b) {
    asm("fma.rn.f32x2 %0, %1, %2, %0;" : "+l"(d) : "l"(a), "l"(b));
}

// ---------------- init / reset --------------------------------------------
__global__ void k_reset() {
    int i = blockIdx.x * blockDim.x + threadIdx.x;
    if (i < NN) { g_deg[i] = 0; g_fill[i] = 0; }
    if (i < NG * NC) g_sums[i] = 0.f;
    if (i < NG) g_cnts[i] = 0.f;
}

// ---------------- degree histogram ----------------------------------------
__global__ void k_hist(const int* __restrict__ ei) {
    int e = blockIdx.x * blockDim.x + threadIdx.x;
    if (e >= NE) return;
    atomicAdd(&g_deg[ei[NE + e]], 1);
}

__global__ void k_dinv() {
    int i = blockIdx.x * blockDim.x + threadIdx.x;
    if (i >= NN) return;
    g_dinv[i] = rsqrtf((float)(g_deg[i] + 1));
}

// ---------------- exclusive scan over g_deg -> g_ptr ----------------------
__global__ void k_scanA() {
    __shared__ int sh[1024];
    int b = blockIdx.x, t = threadIdx.x;
    int base = b * 4096 + t * 4;
    int v[4]; int s = 0;
#pragma unroll
    for (int j = 0; j < 4; ++j) {
        v[j] = (base + j < NN) ? g_deg[base + j] : 0;
        s += v[j];
    }
    sh[t] = s; __syncthreads();
    for (int off = 1; off < 1024; off <<= 1) {
        int x = (t >= off) ? sh[t - off] : 0;
        __syncthreads();
        sh[t] += x;
        __syncthreads();
    }
    int excl = sh[t] - s;
    if (t == 1023) g_bsum[b] = sh[1023];
    int run = excl;
#pragma unroll
    for (int j = 0; j < 4; ++j) {
        if (base + j < NN) g_ptr[base + j] = run;
        run += v[j];
    }
}

__global__ void k_scanSpine() {
    if (threadIdx.x == 0) {
        int acc = 0;
        for (int b = 0; b < 25; ++b) { int x = g_bsum[b]; g_bsum[b] = acc; acc += x; }
        g_ptr[NN] = acc;
    }
}

__global__ void k_scanAdd() {
    int i = blockIdx.x * blockDim.x + threadIdx.x;
    if (i < NN) g_ptr[i] += g_bsum[i / 4096];
}

// ---------------- CSR fill (by destination) -------------------------------
__global__ void k_fill(const int* __restrict__ ei) {
    int e = blockIdx.x * blockDim.x + threadIdx.x;
    if (e >= NE) return;
    int r = ei[e];
    int c = ei[NE + e];
    int pos = g_ptr[c] + atomicAdd(&g_fill[c], 1);
    g_srcs[pos] = r;
    g_nrm[pos]  = g_dinv[r] * g_dinv[c];
}

// ---------------- GEMM1: g_h1 = X @ W1  (FFMA2, 128x128x8 tiles) ----------
// A tile stored DUPLICATED in smem so each 64-bit LDS yields (a, a); B pairs
// are naturally contiguous. Inner product runs entirely on fma.rn.f32x2.
__global__ __launch_bounds__(256) void k_gemm1(const float* __restrict__ X,
                                               const float* __restrict__ W) {
    __shared__ float As2[8][256];   // duplicated A: As2[k][2r] = As2[k][2r+1]
    __shared__ float Bs[8][128];
    int bm = blockIdx.x * 128;
    int tid = threadIdx.x;
    int tx = tid & 15, ty = tid >> 4;         // 16 x 16 thread grid

    ull acc2[8][4];
#pragma unroll
    for (int i = 0; i < 8; ++i)
#pragma unroll
        for (int j = 0; j < 4; ++j) acc2[i][j] = 0ull;

    int ar = tid >> 1, ac = (tid & 1) * 4;    // A load: 128 rows x 8 cols
    int br = tid >> 5, bc = (tid & 31) * 4;   // B load: 8 rows x 128 cols
    int gr = bm + ar;

    for (int k0 = 0; k0 < 128; k0 += 8) {
        float4 av = (gr < NN) ? *(const float4*)(X + (size_t)gr * 128 + k0 + ac)
                              : make_float4(0.f, 0.f, 0.f, 0.f);
        As2[ac + 0][2 * ar] = av.x; As2[ac + 0][2 * ar + 1] = av.x;
        As2[ac + 1][2 * ar] = av.y; As2[ac + 1][2 * ar + 1] = av.y;
        As2[ac + 2][2 * ar] = av.z; As2[ac + 2][2 * ar + 1] = av.z;
        As2[ac + 3][2 * ar] = av.w; As2[ac + 3][2 * ar + 1] = av.w;
        *(float4*)&Bs[br][bc] = *(const float4*)(W + (size_t)(k0 + br) * 128 + bc);
        __syncthreads();
#pragma unroll
        for (int k = 0; k < 8; ++k) {
            const ull* ap = (const ull*)&As2[k][ty * 16];  // 8 x (a,a) pairs
            const ull* bp = (const ull*)&Bs[k][tx * 8];    // 4 x (b0,b1) pairs
            ull ra2[8], rb2[4];
#pragma unroll
            for (int i = 0; i < 8; ++i) ra2[i] = ap[i];
#pragma unroll
            for (int j = 0; j < 4; ++j) rb2[j] = bp[j];
#pragma unroll
            for (int i = 0; i < 8; ++i)
#pragma unroll
                for (int j = 0; j < 4; ++j) ffma2(acc2[i][j], ra2[i], rb2[j]);
        }
        __syncthreads();
    }
#pragma unroll
    for (int i = 0; i < 8; ++i) {
        int row = bm + ty * 8 + i;
        if (row < NN) {
            ull* o = (ull*)(g_h1 + (size_t)row * 128 + tx * 8);
#pragma unroll
            for (int j = 0; j < 4; ++j) o[j] = acc2[i][j];
        }
    }
}

// ------- layer-1 aggregation FUSED with skinny GEMM2 (warp per node) ------
// act = relu(agg1 + b1) kept in registers; h2 = act @ W2 via warp reduce.
__global__ void k_agg1h2(const float* __restrict__ b1,
                         const float* __restrict__ W2) {
    int warp = (blockIdx.x * blockDim.x + threadIdx.x) >> 5;
    int lane = threadIdx.x & 31;
    if (warp >= NN) return;
    int p0 = g_ptr[warp], p1 = g_ptr[warp + 1];
    float d = g_dinv[warp];
    const float4* hs = (const float4*)(g_h1 + (size_t)warp * 128);
    float4 v = hs[lane];
    float w0 = d * d;
    float4 acc = make_float4(w0 * v.x, w0 * v.y, w0 * v.z, w0 * v.w);
    for (int e = p0; e < p1; ++e) {
        int r = g_srcs[e];
        float w = g_nrm[e];
        const float4* hr = (const float4*)(g_h1 + (size_t)r * 128);
        float4 u = hr[lane];
        acc.x += w * u.x; acc.y += w * u.y; acc.z += w * u.z; acc.w += w * u.w;
    }
    float4 bb = ((const float4*)b1)[lane];
    acc.x = fmaxf(acc.x + bb.x, 0.f);
    acc.y = fmaxf(acc.y + bb.y, 0.f);
    acc.z = fmaxf(acc.z + bb.z, 0.f);
    acc.w = fmaxf(acc.w + bb.w, 0.f);

    // h2 = act @ W2  (W2 is [128][2] row-major; lane owns k = 4*lane..4*lane+3)
    const float4* w2p = (const float4*)(W2 + lane * 8);
    float4 wA = w2p[0];   // (W2[k][0],W2[k][1],W2[k+1][0],W2[k+1][1])
    float4 wB = w2p[1];   // (W2[k+2][0],...)
    float s0 = acc.x * wA.x + acc.y * wA.z + acc.z * wB.x + acc.w * wB.z;
    float s1 = acc.x * wA.y + acc.y * wA.w + acc.z * wB.y + acc.w * wB.w;
#pragma unroll
    for (int off = 16; off > 0; off >>= 1) {
        s0 += __shfl_xor_sync(0xffffffffu, s0, off);
        s1 += __shfl_xor_sync(0xffffffffu, s1, off);
    }
    if (lane == 0) {
        g_h2[warp * 2 + 0] = s0;
        g_h2[warp * 2 + 1] = s1;
    }
}

// ---------------- layer-2 aggregation + mean-pool partial -----------------
__global__ void k_agg2pool(const float* __restrict__ b2,
                           const int* __restrict__ batch) {
    __shared__ float s_sums[NG * NC];
    __shared__ float s_cnt[NG];
    int t = threadIdx.x;
    if (t < NG * NC) s_sums[t] = 0.f;
    if (t < NG) s_cnt[t] = 0.f;
    __syncthreads();

    int i = blockIdx.x * blockDim.x + t;
    if (i < NN) {
        float d = g_dinv[i];
        float a0 = d * d * g_h2[i * 2 + 0];
        float a1 = d * d * g_h2[i * 2 + 1];
        int p0 = g_ptr[i], p1 = g_ptr[i + 1];
        for (int e = p0; e < p1; ++e) {
            int r = g_srcs[e];
            float w = g_nrm[e];
            a0 += w * g_h2[r * 2 + 0];
            a1 += w * g_h2[r * 2 + 1];
        }
        a0 += b2[0]; a1 += b2[1];
        int g = batch[i];
        atomicAdd(&s_sums[g * 2 + 0], a0);
        atomicAdd(&s_sums[g * 2 + 1], a1);
        atomicAdd(&s_cnt[g], 1.f);
    }
    __syncthreads();
    if (t < NG * NC) atomicAdd(&g_sums[t], s_sums[t]);
    if (t < NG) atomicAdd(&g_cnts[t], s_cnt[t]);
}

// ---------------- final: mean + log_softmax -------------------------------
__global__ void k_final(float* __restrict__ out) {
    int t = threadIdx.x;
    if (t >= NG) return;
    float c = fmaxf(g_cnts[t], 1.f);
    float p0 = g_sums[t * 2 + 0] / c;
    float p1 = g_sums[t * 2 + 1] / c;
    float m = fmaxf(p0, p1);
    float l = m + logf(expf(p0 - m) + expf(p1 - m));
    out[t * 2 + 0] = p0 - l;
    out[t * 2 + 1] = p1 - l;
}

// ---------------- launch --------------------------------------------------
extern "C" void kernel_launch(void* const* d_in, const int* in_sizes, int n_in,
                              void* d_out, int out_size) {
    const float* x     = (const float*)d_in[0];
    const int*   ei    = (const int*)d_in[1];     // int32 (JAX x64 disabled)
    const int*   batch = (const int*)d_in[2];
    const float* W1    = (const float*)d_in[3];
    const float* b1    = (const float*)d_in[4];
    const float* W2    = (const float*)d_in[5];
    const float* b2    = (const float*)d_in[6];
    float* out = (float*)d_out;

    k_reset<<<(NN + 255) / 256, 256>>>();
    k_hist<<<(NE + 255) / 256, 256>>>(ei);
    k_dinv<<<(NN + 255) / 256, 256>>>();
    k_scanA<<<25, 1024>>>();
    k_scanSpine<<<1, 32>>>();
    k_scanAdd<<<(NN + 255) / 256, 256>>>();
    k_fill<<<(NE + 255) / 256, 256>>>(ei);
    k_gemm1<<<(NN + 127) / 128, 256>>>(x, W1);
    k_agg1h2<<<(NN * 32 + 255) / 256, 256>>>(b1, W2);
    k_agg2pool<<<(NN + 255) / 256, 256>>>(b2, batch);
    k_final<<<1, 32>>>(out);
}

// round 4
// speedup vs baseline: 1.1731x; 1.1596x over previous
#include <cuda_runtime.h>
#include <cuda_bf16.h>
#include <math.h>

#define NN 100000
#define NE 800000
#define NG 16
#define NF 128
#define NH 128
#define NC 2

typedef unsigned long long ull;

// ---------------- persistent scratch (alloc-free rule: __device__ globals) ---
__device__ int   g_deg[NN];
__device__ float g_dinv[NN];
__device__ int   g_ptr[NN + 1];
__device__ int   g_fill[NN];
__device__ int   g_srcs[NE];
__device__ float g_h1[(size_t)NN * NF];   // dinv * (x @ W1)   (pre-scaled!)
__device__ float g_h2[NN * NC];           // dinv * (act @ W2) (pre-scaled!)
__device__ float g_sums[NG * NC];
__device__ float g_cnts[NG];
__device__ int   g_bsum[32];

// ---------------- f32x2 helpers -------------------------------------------
__device__ __forceinline__ void ffma2(ull& d, ull a, ull b) {
    asm("fma.rn.f32x2 %0, %1, %2, %0;" : "+l"(d) : "l"(a), "l"(b));
}
__device__ __forceinline__ ull pk2(float a) {            // (a, a)
    ull r; asm("mov.b64 %0, {%1, %1};" : "=l"(r) : "f"(a)); return r;
}
__device__ __forceinline__ ull mul2(ull a, ull b) {
    ull r; asm("mul.rn.f32x2 %0, %1, %2;" : "=l"(r) : "l"(a), "l"(b)); return r;
}

// ---------------- init / reset --------------------------------------------
__global__ void k_reset() {
    int i = blockIdx.x * blockDim.x + threadIdx.x;
    if (i < NN) { g_deg[i] = 0; g_fill[i] = 0; }
    if (i < NG * NC) g_sums[i] = 0.f;
    if (i < NG) g_cnts[i] = 0.f;
}

// ---------------- degree histogram ----------------------------------------
__global__ void k_hist(const int* __restrict__ ei) {
    int e = blockIdx.x * blockDim.x + threadIdx.x;
    if (e >= NE) return;
    atomicAdd(&g_deg[ei[NE + e]], 1);
}

__global__ void k_dinv() {
    int i = blockIdx.x * blockDim.x + threadIdx.x;
    if (i >= NN) return;
    g_dinv[i] = rsqrtf((float)(g_deg[i] + 1));
}

// ---------------- GEMM1: g_h1 = dinv * (X @ W1)  (FFMA2, 128x128x8) -------
// Launched 4th so ncu's fixed capture slot profiles it.
__global__ __launch_bounds__(256) void k_gemm1(const float* __restrict__ X,
                                               const float* __restrict__ W) {
    __shared__ float As[8][128];
    __shared__ float Bs[8][128];
    int bm = blockIdx.x * 128;
    int tid = threadIdx.x;
    int tx = tid & 15, ty = tid >> 4;         // 16 x 16 thread grid

    ull acc2[8][4];
#pragma unroll
    for (int i = 0; i < 8; ++i)
#pragma unroll
        for (int j = 0; j < 4; ++j) acc2[i][j] = 0ull;

    int ar = tid >> 1, ac = (tid & 1) * 4;    // A load: 128 rows x 8 cols
    int br = tid >> 5, bc = (tid & 31) * 4;   // B load: 8 rows x 128 cols
    int gr = bm + ar;

    for (int k0 = 0; k0 < 128; k0 += 8) {
        float4 av = (gr < NN) ? *(const float4*)(X + (size_t)gr * 128 + k0 + ac)
                              : make_float4(0.f, 0.f, 0.f, 0.f);
        As[ac + 0][ar] = av.x; As[ac + 1][ar] = av.y;
        As[ac + 2][ar] = av.z; As[ac + 3][ar] = av.w;
        *(float4*)&Bs[br][bc] = *(const float4*)(W + (size_t)(k0 + br) * 128 + bc);
        __syncthreads();
#pragma unroll
        for (int k = 0; k < 8; ++k) {
            float4 ra0 = *(const float4*)&As[k][ty * 8];
            float4 ra1 = *(const float4*)&As[k][ty * 8 + 4];
            const ull* bp = (const ull*)&Bs[k][tx * 8];
            ull rb2[4];
#pragma unroll
            for (int j = 0; j < 4; ++j) rb2[j] = bp[j];
            ull a2[8];
            a2[0] = pk2(ra0.x); a2[1] = pk2(ra0.y);
            a2[2] = pk2(ra0.z); a2[3] = pk2(ra0.w);
            a2[4] = pk2(ra1.x); a2[5] = pk2(ra1.y);
            a2[6] = pk2(ra1.z); a2[7] = pk2(ra1.w);
#pragma unroll
            for (int i = 0; i < 8; ++i)
#pragma unroll
                for (int j = 0; j < 4; ++j) ffma2(acc2[i][j], a2[i], rb2[j]);
        }
        __syncthreads();
    }
#pragma unroll
    for (int i = 0; i < 8; ++i) {
        int row = bm + ty * 8 + i;
        if (row < NN) {
            ull dd = pk2(g_dinv[row]);
            ull* o = (ull*)(g_h1 + (size_t)row * 128 + tx * 8);
#pragma unroll
            for (int j = 0; j < 4; ++j) o[j] = mul2(acc2[i][j], dd);
        }
    }
}

// ---------------- exclusive scan over g_deg -> g_ptr ----------------------
__global__ void k_scanA() {
    __shared__ int sh[1024];
    int b = blockIdx.x, t = threadIdx.x;
    int base = b * 4096 + t * 4;
    int v[4]; int s = 0;
#pragma unroll
    for (int j = 0; j < 4; ++j) {
        v[j] = (base + j < NN) ? g_deg[base + j] : 0;
        s += v[j];
    }
    sh[t] = s; __syncthreads();
    for (int off = 1; off < 1024; off <<= 1) {
        int x = (t >= off) ? sh[t - off] : 0;
        __syncthreads();
        sh[t] += x;
        __syncthreads();
    }
    int excl = sh[t] - s;
    if (t == 1023) g_bsum[b] = sh[1023];
    int run = excl;
#pragma unroll
    for (int j = 0; j < 4; ++j) {
        if (base + j < NN) g_ptr[base + j] = run;
        run += v[j];
    }
}

__global__ void k_scanSpine() {
    if (threadIdx.x == 0) {
        int acc = 0;
        for (int b = 0; b < 25; ++b) { int x = g_bsum[b]; g_bsum[b] = acc; acc += x; }
        g_ptr[NN] = acc;
    }
}

__global__ void k_scanAdd() {
    int i = blockIdx.x * blockDim.x + threadIdx.x;
    if (i < NN) g_ptr[i] += g_bsum[i / 4096];
}

// ---------------- CSR fill (index only; norm is factored out) -------------
__global__ void k_fill(const int* __restrict__ ei) {
    int e = blockIdx.x * blockDim.x + threadIdx.x;
    if (e >= NE) return;
    int r = ei[e];
    int c = ei[NE + e];
    int pos = g_ptr[c] + atomicAdd(&g_fill[c], 1);
    g_srcs[pos] = r;
}

// ------- layer-1 aggregation FUSED with skinny GEMM2 (warp per node) ------
// g_h1 rows are pre-scaled by dinv[src]; out[c] = dinv[c]*(sum + self).
// act = relu(out + b1); h2s[c] = dinv[c] * (act @ W2).
__global__ void k_agg1h2(const float* __restrict__ b1,
                         const float* __restrict__ W2) {
    int warp = (blockIdx.x * blockDim.x + threadIdx.x) >> 5;
    int lane = threadIdx.x & 31;
    if (warp >= NN) return;
    int p0 = g_ptr[warp], p1 = g_ptr[warp + 1];
    float d = g_dinv[warp];
    float4 acc = ((const float4*)(g_h1 + (size_t)warp * 128))[lane];  // self (pre-scaled)
    for (int e = p0; e < p1; ++e) {
        int r = g_srcs[e];
        float4 u = ((const float4*)(g_h1 + (size_t)r * 128))[lane];
        acc.x += u.x; acc.y += u.y; acc.z += u.z; acc.w += u.w;
    }
    float4 bb = ((const float4*)b1)[lane];
    acc.x = fmaxf(fmaf(d, acc.x, bb.x), 0.f);
    acc.y = fmaxf(fmaf(d, acc.y, bb.y), 0.f);
    acc.z = fmaxf(fmaf(d, acc.z, bb.z), 0.f);
    acc.w = fmaxf(fmaf(d, acc.w, bb.w), 0.f);

    // h2 = act @ W2  (W2 is [128][2] row-major; lane owns k = 4*lane..4*lane+3)
    const float4* w2p = (const float4*)(W2 + lane * 8);
    float4 wA = w2p[0];
    float4 wB = w2p[1];
    float s0 = acc.x * wA.x + acc.y * wA.z + acc.z * wB.x + acc.w * wB.z;
    float s1 = acc.x * wA.y + acc.y * wA.w + acc.z * wB.y + acc.w * wB.w;
#pragma unroll
    for (int off = 16; off > 0; off >>= 1) {
        s0 += __shfl_xor_sync(0xffffffffu, s0, off);
        s1 += __shfl_xor_sync(0xffffffffu, s1, off);
    }
    if (lane == 0) {
        g_h2[warp * 2 + 0] = d * s0;   // pre-scale for layer-2 factorization
        g_h2[warp * 2 + 1] = d * s1;
    }
}

// ---------------- layer-2 aggregation + mean-pool partial -----------------
__global__ void k_agg2pool(const float* __restrict__ b2,
                           const int* __restrict__ batch) {
    __shared__ float s_sums[NG * NC];
    __shared__ float s_cnt[NG];
    int t = threadIdx.x;
    if (t < NG * NC) s_sums[t] = 0.f;
    if (t < NG) s_cnt[t] = 0.f;
    __syncthreads();

    int i = blockIdx.x * blockDim.x + t;
    if (i < NN) {
        float d = g_dinv[i];
        float a0 = g_h2[i * 2 + 0];   // self (pre-scaled)
        float a1 = g_h2[i * 2 + 1];
        int p0 = g_ptr[i], p1 = g_ptr[i + 1];
        for (int e = p0; e < p1; ++e) {
            int r = g_srcs[e];
            a0 += g_h2[r * 2 + 0];
            a1 += g_h2[r * 2 + 1];
        }
        a0 = fmaf(d, a0, b2[0]);
        a1 = fmaf(d, a1, b2[1]);
        int g = batch[i];
        atomicAdd(&s_sums[g * 2 + 0], a0);
        atomicAdd(&s_sums[g * 2 + 1], a1);
        atomicAdd(&s_cnt[g], 1.f);
    }
    __syncthreads();
    if (t < NG * NC) atomicAdd(&g_sums[t], s_sums[t]);
    if (t < NG) atomicAdd(&g_cnts[t], s_cnt[t]);
}

// ---------------- final: mean + log_softmax -------------------------------
__global__ void k_final(float* __restrict__ out) {
    int t = threadIdx.x;
    if (t >= NG) return;
    float c = fmaxf(g_cnts[t], 1.f);
    float p0 = g_sums[t * 2 + 0] / c;
    float p1 = g_sums[t * 2 + 1] / c;
    float m = fmaxf(p0, p1);
    float l = m + logf(expf(p0 - m) + expf(p1 - m));
    out[t * 2 + 0] = p0 - l;
    out[t * 2 + 1] = p1 - l;
}

// ---------------- launch --------------------------------------------------
extern "C" void kernel_launch(void* const* d_in, const int* in_sizes, int n_in,
                              void* d_out, int out_size) {
    const float* x     = (const float*)d_in[0];
    const int*   ei    = (const int*)d_in[1];     // int32 (JAX x64 disabled)
    const int*   batch = (const int*)d_in[2];
    const float* W1    = (const float*)d_in[3];
    const float* b1    = (const float*)d_in[4];
    const float* W2    = (const float*)d_in[5];
    const float* b2    = (const float*)d_in[6];
    float* out = (float*)d_out;

    k_reset<<<(NN + 255) / 256, 256>>>();
    k_hist<<<(NE + 255) / 256, 256>>>(ei);
    k_dinv<<<(NN + 255) / 256, 256>>>();
    k_gemm1<<<(NN + 127) / 128, 256>>>(x, W1);   // 4th launch -> ncu capture slot
    k_scanA<<<25, 1024>>>();
    k_scanSpine<<<1, 32>>>();
    k_scanAdd<<<(NN + 255) / 256, 256>>>();
    k_fill<<<(NE + 255) / 256, 256>>>(ei);
    k_agg1h2<<<(NN * 32 + 255) / 256, 256>>>(b1, W2);
    k_agg2pool<<<(NN + 255) / 256, 256>>>(b2, batch);
    k_final<<<1, 32>>>(out);
}

// round 5
// speedup vs baseline: 1.5690x; 1.3375x over previous
#include <cuda_runtime.h>
#include <cuda_bf16.h>
#include <math.h>

#define NN 100000
#define NE 800000
#define NG 16
#define NF 128
#define NH 128
#define NC 2

typedef unsigned long long ull;

// ---------------- persistent scratch (alloc-free rule: __device__ globals) ---
__device__ int   g_deg[NN];
__device__ float g_dinv[NN];
__device__ int   g_ptr[NN + 1];
__device__ int   g_fill[NN];
__device__ int   g_srcs[NE];
__device__ float g_h1[(size_t)NN * NF];   // dinv * (x @ W1)   (pre-scaled)
__device__ float g_h2[NN * NC];           // dinv * (act @ W2) (pre-scaled)
__device__ float g_sums[NG * NC];
__device__ float g_cnts[NG];
__device__ int   g_bsum[32];

// ---------------- helpers -------------------------------------------------
__device__ __forceinline__ unsigned f2tf32(float x) {
    unsigned r;
    asm("cvt.rna.tf32.f32 %0, %1;" : "=r"(r) : "f"(x));
    return r;
}

__device__ __forceinline__ void mma_tf32(float& c0, float& c1, float& c2, float& c3,
                                         unsigned a0, unsigned a1, unsigned a2, unsigned a3,
                                         unsigned b0, unsigned b1) {
    asm("mma.sync.aligned.m16n8k8.row.col.f32.tf32.tf32.f32 "
        "{%0,%1,%2,%3}, {%4,%5,%6,%7}, {%8,%9}, {%0,%1,%2,%3};"
        : "+f"(c0), "+f"(c1), "+f"(c2), "+f"(c3)
        : "r"(a0), "r"(a1), "r"(a2), "r"(a3), "r"(b0), "r"(b1));
}

// ---------------- init / reset --------------------------------------------
__global__ void k_reset() {
    int i = blockIdx.x * blockDim.x + threadIdx.x;
    if (i < NN) { g_deg[i] = 0; g_fill[i] = 0; }
    if (i < NG * NC) g_sums[i] = 0.f;
    if (i < NG) g_cnts[i] = 0.f;
}

// ---------------- degree histogram ----------------------------------------
__global__ void k_hist(const int* __restrict__ ei) {
    int e = blockIdx.x * blockDim.x + threadIdx.x;
    if (e >= NE) return;
    atomicAdd(&g_deg[ei[NE + e]], 1);
}

__global__ void k_dinv() {
    int i = blockIdx.x * blockDim.x + threadIdx.x;
    if (i >= NN) return;
    g_dinv[i] = rsqrtf((float)(g_deg[i] + 1));
}

// ---------------- GEMM1: g_h1 = dinv * (X @ W1)  (tf32 tensor-core MMA) ---
// 128x128 tile per CTA, K streamed in 32-wide smem tiles. 8 warps: warp w
// owns rows [w*16, w*16+16) x all 128 cols (16 m16n8 tiles). Smem strides
// (36, 136) make all fragment LDS patterns bank-conflict-free.
__global__ __launch_bounds__(256) void k_gemm1(const float* __restrict__ X,
                                               const float* __restrict__ W) {
    __shared__ float As[128][36];    // [row][k]  stride%32 == 4
    __shared__ float Bs[32][136];    // [k][n]    stride%32 == 8
    int tid  = threadIdx.x;
    int warp = tid >> 5, lane = tid & 31;
    int g    = lane >> 2, tig = lane & 3;       // groupID, thread-in-group
    int bm   = blockIdx.x * 128;
    int wrow = warp * 16;

    float c[16][4];
#pragma unroll
    for (int nt = 0; nt < 16; ++nt)
#pragma unroll
        for (int j = 0; j < 4; ++j) c[nt][j] = 0.f;

    for (int k0 = 0; k0 < 128; k0 += 32) {
        // load A tile: 128 rows x 32 cols (1024 float4, 4 per thread)
#pragma unroll
        for (int i = 0; i < 4; ++i) {
            int idx = tid + i * 256;
            int row = idx >> 3, c4 = (idx & 7) * 4;
            int grow = bm + row;
            float4 v = (grow < NN)
                ? *(const float4*)(X + (size_t)grow * 128 + k0 + c4)
                : make_float4(0.f, 0.f, 0.f, 0.f);
            As[row][c4 + 0] = __uint_as_float(f2tf32(v.x));
            As[row][c4 + 1] = __uint_as_float(f2tf32(v.y));
            As[row][c4 + 2] = __uint_as_float(f2tf32(v.z));
            As[row][c4 + 3] = __uint_as_float(f2tf32(v.w));
        }
        // load B tile: 32 rows x 128 cols
#pragma unroll
        for (int i = 0; i < 4; ++i) {
            int idx = tid + i * 256;
            int row = idx >> 5, cc = (idx & 31) * 4;
            float4 v = *(const float4*)(W + (size_t)(k0 + row) * 128 + cc);
            Bs[row][cc + 0] = __uint_as_float(f2tf32(v.x));
            Bs[row][cc + 1] = __uint_as_float(f2tf32(v.y));
            Bs[row][cc + 2] = __uint_as_float(f2tf32(v.z));
            Bs[row][cc + 3] = __uint_as_float(f2tf32(v.w));
        }
        __syncthreads();
#pragma unroll
        for (int ks = 0; ks < 4; ++ks) {
            int kk = ks * 8;
            unsigned a0 = __float_as_uint(As[wrow + g    ][kk + tig    ]);
            unsigned a1 = __float_as_uint(As[wrow + g + 8][kk + tig    ]);
            unsigned a2 = __float_as_uint(As[wrow + g    ][kk + tig + 4]);
            unsigned a3 = __float_as_uint(As[wrow + g + 8][kk + tig + 4]);
#pragma unroll
            for (int nt = 0; nt < 16; ++nt) {
                unsigned b0 = __float_as_uint(Bs[kk + tig    ][nt * 8 + g]);
                unsigned b1 = __float_as_uint(Bs[kk + tig + 4][nt * 8 + g]);
                mma_tf32(c[nt][0], c[nt][1], c[nt][2], c[nt][3],
                         a0, a1, a2, a3, b0, b1);
            }
        }
        __syncthreads();
    }

    // epilogue: scale by dinv[row], store
    int r0 = bm + wrow + g;
    int r1 = r0 + 8;
    float d0 = (r0 < NN) ? g_dinv[r0] : 0.f;
    float d1 = (r1 < NN) ? g_dinv[r1] : 0.f;
#pragma unroll
    for (int nt = 0; nt < 16; ++nt) {
        int col = nt * 8 + tig * 2;
        if (r0 < NN) {
            float2 v = make_float2(d0 * c[nt][0], d0 * c[nt][1]);
            *(float2*)(g_h1 + (size_t)r0 * 128 + col) = v;
        }
        if (r1 < NN) {
            float2 v = make_float2(d1 * c[nt][2], d1 * c[nt][3]);
            *(float2*)(g_h1 + (size_t)r1 * 128 + col) = v;
        }
    }
}

// ---------------- exclusive scan over g_deg -> g_ptr ----------------------
__global__ void k_scanA() {
    __shared__ int sh[1024];
    int b = blockIdx.x, t = threadIdx.x;
    int base = b * 4096 + t * 4;
    int v[4]; int s = 0;
#pragma unroll
    for (int j = 0; j < 4; ++j) {
        v[j] = (base + j < NN) ? g_deg[base + j] : 0;
        s += v[j];
    }
    sh[t] = s; __syncthreads();
    for (int off = 1; off < 1024; off <<= 1) {
        int x = (t >= off) ? sh[t - off] : 0;
        __syncthreads();
        sh[t] += x;
        __syncthreads();
    }
    int excl = sh[t] - s;
    if (t == 1023) g_bsum[b] = sh[1023];
    int run = excl;
#pragma unroll
    for (int j = 0; j < 4; ++j) {
        if (base + j < NN) g_ptr[base + j] = run;
        run += v[j];
    }
}

__global__ void k_scanSpine() {
    if (threadIdx.x == 0) {
        int acc = 0;
        for (int b = 0; b < 25; ++b) { int x = g_bsum[b]; g_bsum[b] = acc; acc += x; }
        g_ptr[NN] = acc;
    }
}

__global__ void k_scanAdd() {
    int i = blockIdx.x * blockDim.x + threadIdx.x;
    if (i < NN) g_ptr[i] += g_bsum[i / 4096];
}

// ---------------- CSR fill (index only; norm factored out) ----------------
__global__ void k_fill(const int* __restrict__ ei) {
    int e = blockIdx.x * blockDim.x + threadIdx.x;
    if (e >= NE) return;
    int r = ei[e];
    int c = ei[NE + e];
    int pos = g_ptr[c] + atomicAdd(&g_fill[c], 1);
    g_srcs[pos] = r;
}

// ------- layer-1 aggregation FUSED with skinny GEMM2 (warp per node) ------
__global__ void k_agg1h2(const float* __restrict__ b1,
                         const float* __restrict__ W2) {
    int warp = (blockIdx.x * blockDim.x + threadIdx.x) >> 5;
    int lane = threadIdx.x & 31;
    if (warp >= NN) return;
    int p0 = g_ptr[warp], p1 = g_ptr[warp + 1];
    float d = g_dinv[warp];
    float4 acc = ((const float4*)(g_h1 + (size_t)warp * 128))[lane];  // self (pre-scaled)
    for (int e = p0; e < p1; ++e) {
        int r = g_srcs[e];
        float4 u = ((const float4*)(g_h1 + (size_t)r * 128))[lane];
        acc.x += u.x; acc.y += u.y; acc.z += u.z; acc.w += u.w;
    }
    float4 bb = ((const float4*)b1)[lane];
    acc.x = fmaxf(fmaf(d, acc.x, bb.x), 0.f);
    acc.y = fmaxf(fmaf(d, acc.y, bb.y), 0.f);
    acc.z = fmaxf(fmaf(d, acc.z, bb.z), 0.f);
    acc.w = fmaxf(fmaf(d, acc.w, bb.w), 0.f);

    const float4* w2p = (const float4*)(W2 + lane * 8);
    float4 wA = w2p[0];
    float4 wB = w2p[1];
    float s0 = acc.x * wA.x + acc.y * wA.z + acc.z * wB.x + acc.w * wB.z;
    float s1 = acc.x * wA.y + acc.y * wA.w + acc.z * wB.y + acc.w * wB.w;
#pragma unroll
    for (int off = 16; off > 0; off >>= 1) {
        s0 += __shfl_xor_sync(0xffffffffu, s0, off);
        s1 += __shfl_xor_sync(0xffffffffu, s1, off);
    }
    if (lane == 0) {
        g_h2[warp * 2 + 0] = d * s0;
        g_h2[warp * 2 + 1] = d * s1;
    }
}

// ---------------- layer-2 aggregation + mean-pool partial -----------------
__global__ void k_agg2pool(const float* __restrict__ b2,
                           const int* __restrict__ batch) {
    __shared__ float s_sums[NG * NC];
    __shared__ float s_cnt[NG];
    int t = threadIdx.x;
    if (t < NG * NC) s_sums[t] = 0.f;
    if (t < NG) s_cnt[t] = 0.f;
    __syncthreads();

    int i = blockIdx.x * blockDim.x + t;
    if (i < NN) {
        float d = g_dinv[i];
        float a0 = g_h2[i * 2 + 0];
        float a1 = g_h2[i * 2 + 1];
        int p0 = g_ptr[i], p1 = g_ptr[i + 1];
        for (int e = p0; e < p1; ++e) {
            int r = g_srcs[e];
            a0 += g_h2[r * 2 + 0];
            a1 += g_h2[r * 2 + 1];
        }
        a0 = fmaf(d, a0, b2[0]);
        a1 = fmaf(d, a1, b2[1]);
        int g = batch[i];
        atomicAdd(&s_sums[g * 2 + 0], a0);
        atomicAdd(&s_sums[g * 2 + 1], a1);
        atomicAdd(&s_cnt[g], 1.f);
    }
    __syncthreads();
    if (t < NG * NC) atomicAdd(&g_sums[t], s_sums[t]);
    if (t < NG) atomicAdd(&g_cnts[t], s_cnt[t]);
}

// ---------------- final: mean + log_softmax -------------------------------
__global__ void k_final(float* __restrict__ out) {
    int t = threadIdx.x;
    if (t >= NG) return;
    float c = fmaxf(g_cnts[t], 1.f);
    float p0 = g_sums[t * 2 + 0] / c;
    float p1 = g_sums[t * 2 + 1] / c;
    float m = fmaxf(p0, p1);
    float l = m + logf(expf(p0 - m) + expf(p1 - m));
    out[t * 2 + 0] = p0 - l;
    out[t * 2 + 1] = p1 - l;
}

// ---------------- launch --------------------------------------------------
extern "C" void kernel_launch(void* const* d_in, const int* in_sizes, int n_in,
                              void* d_out, int out_size) {
    const float* x     = (const float*)d_in[0];
    const int*   ei    = (const int*)d_in[1];     // int32 (JAX x64 disabled)
    const int*   batch = (const int*)d_in[2];
    const float* W1    = (const float*)d_in[3];
    const float* b1    = (const float*)d_in[4];
    const float* W2    = (const float*)d_in[5];
    const float* b2    = (const float*)d_in[6];
    float* out = (float*)d_out;

    k_reset<<<(NN + 255) / 256, 256>>>();
    k_hist<<<(NE + 255) / 256, 256>>>(ei);
    k_dinv<<<(NN + 255) / 256, 256>>>();
    k_gemm1<<<(NN + 127) / 128, 256>>>(x, W1);   // 4th launch -> ncu capture slot
    k_scanA<<<25, 1024>>>();
    k_scanSpine<<<1, 32>>>();
    k_scanAdd<<<(NN + 255) / 256, 256>>>();
    k_fill<<<(NE + 255) / 256, 256>>>(ei);
    k_agg1h2<<<(NN * 32 + 255) / 256, 256>>>(b1, W2);
    k_agg2pool<<<(NN + 255) / 256, 256>>>(b2, batch);
    k_final<<<1, 32>>>(out);
}

// round 6
// speedup vs baseline: 1.7810x; 1.1351x over previous
#include <cuda_runtime.h>
#include <cuda_bf16.h>
#include <math.h>

#define NN 100000
#define NE 800000
#define NG 16
#define NF 128
#define NH 128
#define NC 2

typedef unsigned long long ull;

// ---------------- persistent scratch (alloc-free rule: __device__ globals) ---
__device__ int    g_deg[NN];
__device__ float  g_dinv[NN];
__device__ int    g_ptr[NN + 1];
__device__ int    g_fill[NN];
__device__ int    g_srcs[NE];
__device__ float  g_h1[(size_t)NN * NF];   // dinv * (x @ W1)   (pre-scaled)
__device__ float  g_h2[NN * NC];           // dinv * (act @ W2) (pre-scaled)
__device__ float  g_sums[NG * NC];
__device__ float  g_cnts[NG];
__device__ int    g_bsum[32];
__device__ float4 g_wfrag[16 * 8 * 32];    // W1 in tf32 mma-fragment order

// ---------------- helpers -------------------------------------------------
__device__ __forceinline__ unsigned f2tf32(float x) {
    unsigned r;
    asm("cvt.rna.tf32.f32 %0, %1;" : "=r"(r) : "f"(x));
    return r;
}

__device__ __forceinline__ void mma_tf32(float& c0, float& c1, float& c2, float& c3,
                                         unsigned a0, unsigned a1, unsigned a2, unsigned a3,
                                         unsigned b0, unsigned b1) {
    asm("mma.sync.aligned.m16n8k8.row.col.f32.tf32.tf32.f32 "
        "{%0,%1,%2,%3}, {%4,%5,%6,%7}, {%8,%9}, {%0,%1,%2,%3};"
        : "+f"(c0), "+f"(c1), "+f"(c2), "+f"(c3)
        : "r"(a0), "r"(a1), "r"(a2), "r"(a3), "r"(b0), "r"(b1));
}

// ---------------- reset + W1 fragment transform (one launch) --------------
// Fragment layout per (kg, ntp, lane): lane = g*4+tig (g=lane>>2, tig=lane&3)
//   b0(nt=2ntp)   = W[kg*8+tig  ][ntp*16 + g]
//   b1(nt=2ntp)   = W[kg*8+tig+4][ntp*16 + g]
//   b0(nt=2ntp+1) = W[kg*8+tig  ][ntp*16 + 8 + g]
//   b1(nt=2ntp+1) = W[kg*8+tig+4][ntp*16 + 8 + g]
__global__ void k_reset(const float* __restrict__ W) {
    int i = blockIdx.x * blockDim.x + threadIdx.x;
    if (i < NN) { g_deg[i] = 0; g_fill[i] = 0; }
    if (i < NG * NC) g_sums[i] = 0.f;
    if (i < NG) g_cnts[i] = 0.f;
    if (i < 16 * 8 * 32) {
        int lane = i & 31, ntp = (i >> 5) & 7, kg = i >> 8;
        int g = lane >> 2, tig = lane & 3;
        int klo = kg * 8 + tig, khi = klo + 4;
        int n0 = ntp * 16 + g, n1 = n0 + 8;
        float4 f;
        f.x = __uint_as_float(f2tf32(W[klo * 128 + n0]));
        f.y = __uint_as_float(f2tf32(W[khi * 128 + n0]));
        f.z = __uint_as_float(f2tf32(W[klo * 128 + n1]));
        f.w = __uint_as_float(f2tf32(W[khi * 128 + n1]));
        g_wfrag[i] = f;
    }
}

// ---------------- degree histogram ----------------------------------------
__global__ void k_hist(const int* __restrict__ ei) {
    int e = blockIdx.x * blockDim.x + threadIdx.x;
    if (e >= NE) return;
    atomicAdd(&g_deg[ei[NE + e]], 1);
}

__global__ void k_dinv() {
    int i = blockIdx.x * blockDim.x + threadIdx.x;
    if (i >= NN) return;
    g_dinv[i] = rsqrtf((float)(g_deg[i] + 1));
}

// ---------------- GEMM1: g_h1 = dinv * (X @ W1)  (tf32 MMA, frag-B) -------
// 128x128 tile per CTA, K streamed 32-wide. B comes from g_wfrag: one
// LDS.128 feeds two mma's. A stays in smem (stride 36 -> conflict-free).
__global__ __launch_bounds__(256) void k_gemm1(const float* __restrict__ X) {
    __shared__ float  As[128][36];
    __shared__ float4 Wfs[1024];          // [ks][ntp][lane] for current K tile
    int tid  = threadIdx.x;
    int warp = tid >> 5, lane = tid & 31;
    int g    = lane >> 2, tig = lane & 3;
    int bm   = blockIdx.x * 128;
    int wrow = warp * 16;

    float c[16][4];
#pragma unroll
    for (int nt = 0; nt < 16; ++nt)
#pragma unroll
        for (int j = 0; j < 4; ++j) c[nt][j] = 0.f;

    for (int k0 = 0; k0 < 128; k0 += 32) {
        // A tile: 128 rows x 32 cols, tf32-converted on store
#pragma unroll
        for (int i = 0; i < 4; ++i) {
            int idx = tid + i * 256;
            int row = idx >> 3, c4 = (idx & 7) * 4;
            int grow = bm + row;
            float4 v = (grow < NN)
                ? *(const float4*)(X + (size_t)grow * 128 + k0 + c4)
                : make_float4(0.f, 0.f, 0.f, 0.f);
            As[row][c4 + 0] = __uint_as_float(f2tf32(v.x));
            As[row][c4 + 1] = __uint_as_float(f2tf32(v.y));
            As[row][c4 + 2] = __uint_as_float(f2tf32(v.z));
            As[row][c4 + 3] = __uint_as_float(f2tf32(v.w));
        }
        // B fragments for this K tile: contiguous 16KB block, coalesced copy
        {
            const float4* wsrc = g_wfrag + (k0 >> 3) * 256;
#pragma unroll
            for (int i = 0; i < 4; ++i) {
                int idx = tid + i * 256;
                Wfs[idx] = wsrc[idx];
            }
        }
        __syncthreads();
#pragma unroll
        for (int ks = 0; ks < 4; ++ks) {
            int kk = ks * 8;
            unsigned a0 = __float_as_uint(As[wrow + g    ][kk + tig    ]);
            unsigned a1 = __float_as_uint(As[wrow + g + 8][kk + tig    ]);
            unsigned a2 = __float_as_uint(As[wrow + g    ][kk + tig + 4]);
            unsigned a3 = __float_as_uint(As[wrow + g + 8][kk + tig + 4]);
            const float4* wp = &Wfs[ks * 256 + lane];
#pragma unroll
            for (int ntp = 0; ntp < 8; ++ntp) {
                float4 bf = wp[ntp * 32];
                mma_tf32(c[2 * ntp][0], c[2 * ntp][1], c[2 * ntp][2], c[2 * ntp][3],
                         a0, a1, a2, a3,
                         __float_as_uint(bf.x), __float_as_uint(bf.y));
                mma_tf32(c[2 * ntp + 1][0], c[2 * ntp + 1][1], c[2 * ntp + 1][2], c[2 * ntp + 1][3],
                         a0, a1, a2, a3,
                         __float_as_uint(bf.z), __float_as_uint(bf.w));
            }
        }
        __syncthreads();
    }

    // epilogue: scale by dinv[row], store
    int r0 = bm + wrow + g;
    int r1 = r0 + 8;
    float d0 = (r0 < NN) ? g_dinv[r0] : 0.f;
    float d1 = (r1 < NN) ? g_dinv[r1] : 0.f;
#pragma unroll
    for (int nt = 0; nt < 16; ++nt) {
        int col = nt * 8 + tig * 2;
        if (r0 < NN) {
            float2 v = make_float2(d0 * c[nt][0], d0 * c[nt][1]);
            *(float2*)(g_h1 + (size_t)r0 * 128 + col) = v;
        }
        if (r1 < NN) {
            float2 v = make_float2(d1 * c[nt][2], d1 * c[nt][3]);
            *(float2*)(g_h1 + (size_t)r1 * 128 + col) = v;
        }
    }
}

// ---------------- exclusive scan over g_deg -> g_ptr ----------------------
__global__ void k_scanA() {
    __shared__ int sh[1024];
    int b = blockIdx.x, t = threadIdx.x;
    int base = b * 4096 + t * 4;
    int v[4]; int s = 0;
#pragma unroll
    for (int j = 0; j < 4; ++j) {
        v[j] = (base + j < NN) ? g_deg[base + j] : 0;
        s += v[j];
    }
    sh[t] = s; __syncthreads();
    for (int off = 1; off < 1024; off <<= 1) {
        int x = (t >= off) ? sh[t - off] : 0;
        __syncthreads();
        sh[t] += x;
        __syncthreads();
    }
    int excl = sh[t] - s;
    if (t == 1023) g_bsum[b] = sh[1023];
    int run = excl;
#pragma unroll
    for (int j = 0; j < 4; ++j) {
        if (base + j < NN) g_ptr[base + j] = run;
        run += v[j];
    }
}

__global__ void k_scanSpine() {
    if (threadIdx.x == 0) {
        int acc = 0;
        for (int b = 0; b < 25; ++b) { int x = g_bsum[b]; g_bsum[b] = acc; acc += x; }
        g_ptr[NN] = acc;
    }
}

__global__ void k_scanAdd() {
    int i = blockIdx.x * blockDim.x + threadIdx.x;
    if (i < NN) g_ptr[i] += g_bsum[i / 4096];
}

// ---------------- CSR fill (index only; norm factored out) ----------------
__global__ void k_fill(const int* __restrict__ ei) {
    int e = blockIdx.x * blockDim.x + threadIdx.x;
    if (e >= NE) return;
    int r = ei[e];
    int c = ei[NE + e];
    int pos = g_ptr[c] + atomicAdd(&g_fill[c], 1);
    g_srcs[pos] = r;
}

// ------- layer-1 aggregation FUSED with skinny GEMM2 (warp per node) ------
__global__ void k_agg1h2(const float* __restrict__ b1,
                         const float* __restrict__ W2) {
    int warp = (blockIdx.x * blockDim.x + threadIdx.x) >> 5;
    int lane = threadIdx.x & 31;
    if (warp >= NN) return;
    int p0 = g_ptr[warp], p1 = g_ptr[warp + 1];
    float d = g_dinv[warp];
    float4 acc = ((const float4*)(g_h1 + (size_t)warp * 128))[lane];  // self (pre-scaled)
    for (int e = p0; e < p1; ++e) {
        int r = g_srcs[e];
        float4 u = ((const float4*)(g_h1 + (size_t)r * 128))[lane];
        acc.x += u.x; acc.y += u.y; acc.z += u.z; acc.w += u.w;
    }
    float4 bb = ((const float4*)b1)[lane];
    acc.x = fmaxf(fmaf(d, acc.x, bb.x), 0.f);
    acc.y = fmaxf(fmaf(d, acc.y, bb.y), 0.f);
    acc.z = fmaxf(fmaf(d, acc.z, bb.z), 0.f);
    acc.w = fmaxf(fmaf(d, acc.w, bb.w), 0.f);

    const float4* w2p = (const float4*)(W2 + lane * 8);
    float4 wA = w2p[0];
    float4 wB = w2p[1];
    float s0 = acc.x * wA.x + acc.y * wA.z + acc.z * wB.x + acc.w * wB.z;
    float s1 = acc.x * wA.y + acc.y * wA.w + acc.z * wB.y + acc.w * wB.w;
#pragma unroll
    for (int off = 16; off > 0; off >>= 1) {
        s0 += __shfl_xor_sync(0xffffffffu, s0, off);
        s1 += __shfl_xor_sync(0xffffffffu, s1, off);
    }
    if (lane == 0) {
        g_h2[warp * 2 + 0] = d * s0;
        g_h2[warp * 2 + 1] = d * s1;
    }
}

// ---------------- layer-2 aggregation + mean-pool partial -----------------
__global__ void k_agg2pool(const float* __restrict__ b2,
                           const int* __restrict__ batch) {
    __shared__ float s_sums[NG * NC];
    __shared__ float s_cnt[NG];
    int t = threadIdx.x;
    if (t < NG * NC) s_sums[t] = 0.f;
    if (t < NG) s_cnt[t] = 0.f;
    __syncthreads();

    int i = blockIdx.x * blockDim.x + t;
    if (i < NN) {
        float d = g_dinv[i];
        float a0 = g_h2[i * 2 + 0];
        float a1 = g_h2[i * 2 + 1];
        int p0 = g_ptr[i], p1 = g_ptr[i + 1];
        for (int e = p0; e < p1; ++e) {
            int r = g_srcs[e];
            a0 += g_h2[r * 2 + 0];
            a1 += g_h2[r * 2 + 1];
        }
        a0 = fmaf(d, a0, b2[0]);
        a1 = fmaf(d, a1, b2[1]);
        int g = batch[i];
        atomicAdd(&s_sums[g * 2 + 0], a0);
        atomicAdd(&s_sums[g * 2 + 1], a1);
        atomicAdd(&s_cnt[g], 1.f);
    }
    __syncthreads();
    if (t < NG * NC) atomicAdd(&g_sums[t], s_sums[t]);
    if (t < NG) atomicAdd(&g_cnts[t], s_cnt[t]);
}

// ---------------- final: mean + log_softmax -------------------------------
__global__ void k_final(float* __restrict__ out) {
    int t = threadIdx.x;
    if (t >= NG) return;
    float c = fmaxf(g_cnts[t], 1.f);
    float p0 = g_sums[t * 2 + 0] / c;
    float p1 = g_sums[t * 2 + 1] / c;
    float m = fmaxf(p0, p1);
    float l = m + logf(expf(p0 - m) + expf(p1 - m));
    out[t * 2 + 0] = p0 - l;
    out[t * 2 + 1] = p1 - l;
}

// ---------------- launch --------------------------------------------------
extern "C" void kernel_launch(void* const* d_in, const int* in_sizes, int n_in,
                              void* d_out, int out_size) {
    const float* x     = (const float*)d_in[0];
    const int*   ei    = (const int*)d_in[1];     // int32 (JAX x64 disabled)
    const int*   batch = (const int*)d_in[2];
    const float* W1    = (const float*)d_in[3];
    const float* b1    = (const float*)d_in[4];
    const float* W2    = (const float*)d_in[5];
    const float* b2    = (const float*)d_in[6];
    float* out = (float*)d_out;

    k_reset<<<(NN + 255) / 256, 256>>>(W1);       // also builds g_wfrag
    k_hist<<<(NE + 255) / 256, 256>>>(ei);
    k_dinv<<<(NN + 255) / 256, 256>>>();
    k_gemm1<<<(NN + 127) / 128, 256>>>(x);        // 4th launch -> ncu capture slot
    k_scanA<<<25, 1024>>>();
    k_scanSpine<<<1, 32>>>();
    k_scanAdd<<<(NN + 255) / 256, 256>>>();
    k_fill<<<(NE + 255) / 256, 256>>>(ei);
    k_agg1h2<<<(NN * 32 + 255) / 256, 256>>>(b1, W2);
    k_agg2pool<<<(NN + 255) / 256, 256>>>(b2, batch);
    k_final<<<1, 32>>>(out);
}

// round 7
// speedup vs baseline: 1.9386x; 1.0885x over previous
#include <cuda_runtime.h>
#include <cuda_bf16.h>
#include <math.h>

#define NN 100000
#define NE 800000
#define NG 16
#define NF 128
#define NH 128
#define NC 2

typedef unsigned long long ull;

// ---------------- persistent scratch (alloc-free rule: __device__ globals) ---
__device__ int            g_deg[NN];
__device__ float          g_dinv[NN];
__device__ int            g_ptr[NN + 1];
__device__ int            g_fill[NN];
__device__ int            g_srcs[NE];
__device__ __nv_bfloat16  g_h1b[(size_t)NN * NF];  // bf16(dinv * (x @ W1))
__device__ float          g_h2[NN * NC];           // dinv * (act @ W2)
__device__ float          g_sums[NG * NC];
__device__ float          g_cnts[NG];
__device__ int            g_bsum[32];
__device__ float4         g_wfrag[16 * 8 * 32];    // W1 in tf32 mma-fragment order

// ---------------- helpers -------------------------------------------------
__device__ __forceinline__ unsigned f2tf32(float x) {
    unsigned r;
    asm("cvt.rna.tf32.f32 %0, %1;" : "=r"(r) : "f"(x));
    return r;
}

__device__ __forceinline__ void mma_tf32(float& c0, float& c1, float& c2, float& c3,
                                         unsigned a0, unsigned a1, unsigned a2, unsigned a3,
                                         unsigned b0, unsigned b1) {
    asm("mma.sync.aligned.m16n8k8.row.col.f32.tf32.tf32.f32 "
        "{%0,%1,%2,%3}, {%4,%5,%6,%7}, {%8,%9}, {%0,%1,%2,%3};"
        : "+f"(c0), "+f"(c1), "+f"(c2), "+f"(c3)
        : "r"(a0), "r"(a1), "r"(a2), "r"(a3), "r"(b0), "r"(b1));
}

// ---------------- reset + W1 fragment transform (one launch) --------------
__global__ void k_reset(const float* __restrict__ W) {
    int i = blockIdx.x * blockDim.x + threadIdx.x;
    if (i < NN) { g_deg[i] = 0; g_fill[i] = 0; }
    if (i < NG * NC) g_sums[i] = 0.f;
    if (i < NG) g_cnts[i] = 0.f;
    if (i < 16 * 8 * 32) {
        int lane = i & 31, ntp = (i >> 5) & 7, kg = i >> 8;
        int g = lane >> 2, tig = lane & 3;
        int klo = kg * 8 + tig, khi = klo + 4;
        int n0 = ntp * 16 + g, n1 = n0 + 8;
        float4 f;
        f.x = __uint_as_float(f2tf32(W[klo * 128 + n0]));
        f.y = __uint_as_float(f2tf32(W[khi * 128 + n0]));
        f.z = __uint_as_float(f2tf32(W[klo * 128 + n1]));
        f.w = __uint_as_float(f2tf32(W[khi * 128 + n1]));
        g_wfrag[i] = f;
    }
}

// ---------------- degree histogram ----------------------------------------
__global__ void k_hist(const int* __restrict__ ei) {
    int e = blockIdx.x * blockDim.x + threadIdx.x;
    if (e >= NE) return;
    atomicAdd(&g_deg[ei[NE + e]], 1);
}

__global__ void k_dinv() {
    int i = blockIdx.x * blockDim.x + threadIdx.x;
    if (i >= NN) return;
    g_dinv[i] = rsqrtf((float)(g_deg[i] + 1));
}

// ---------------- GEMM1: g_h1b = bf16(dinv * (X @ W1))  (tf32 MMA) --------
__global__ __launch_bounds__(256) void k_gemm1(const float* __restrict__ X) {
    __shared__ float  As[128][36];
    __shared__ float4 Wfs[1024];
    int tid  = threadIdx.x;
    int warp = tid >> 5, lane = tid & 31;
    int g    = lane >> 2, tig = lane & 3;
    int bm   = blockIdx.x * 128;
    int wrow = warp * 16;

    float c[16][4];
#pragma unroll
    for (int nt = 0; nt < 16; ++nt)
#pragma unroll
        for (int j = 0; j < 4; ++j) c[nt][j] = 0.f;

    for (int k0 = 0; k0 < 128; k0 += 32) {
#pragma unroll
        for (int i = 0; i < 4; ++i) {
            int idx = tid + i * 256;
            int row = idx >> 3, c4 = (idx & 7) * 4;
            int grow = bm + row;
            float4 v = (grow < NN)
                ? *(const float4*)(X + (size_t)grow * 128 + k0 + c4)
                : make_float4(0.f, 0.f, 0.f, 0.f);
            As[row][c4 + 0] = __uint_as_float(f2tf32(v.x));
            As[row][c4 + 1] = __uint_as_float(f2tf32(v.y));
            As[row][c4 + 2] = __uint_as_float(f2tf32(v.z));
            As[row][c4 + 3] = __uint_as_float(f2tf32(v.w));
        }
        {
            const float4* wsrc = g_wfrag + (k0 >> 3) * 256;
#pragma unroll
            for (int i = 0; i < 4; ++i) {
                int idx = tid + i * 256;
                Wfs[idx] = wsrc[idx];
            }
        }
        __syncthreads();
#pragma unroll
        for (int ks = 0; ks < 4; ++ks) {
            int kk = ks * 8;
            unsigned a0 = __float_as_uint(As[wrow + g    ][kk + tig    ]);
            unsigned a1 = __float_as_uint(As[wrow + g + 8][kk + tig    ]);
            unsigned a2 = __float_as_uint(As[wrow + g    ][kk + tig + 4]);
            unsigned a3 = __float_as_uint(As[wrow + g + 8][kk + tig + 4]);
            const float4* wp = &Wfs[ks * 256 + lane];
#pragma unroll
            for (int ntp = 0; ntp < 8; ++ntp) {
                float4 bf = wp[ntp * 32];
                mma_tf32(c[2 * ntp][0], c[2 * ntp][1], c[2 * ntp][2], c[2 * ntp][3],
                         a0, a1, a2, a3,
                         __float_as_uint(bf.x), __float_as_uint(bf.y));
                mma_tf32(c[2 * ntp + 1][0], c[2 * ntp + 1][1], c[2 * ntp + 1][2], c[2 * ntp + 1][3],
                         a0, a1, a2, a3,
                         __float_as_uint(bf.z), __float_as_uint(bf.w));
            }
        }
        __syncthreads();
    }

    // epilogue: scale by dinv[row], store bf16
    int r0 = bm + wrow + g;
    int r1 = r0 + 8;
    float d0 = (r0 < NN) ? g_dinv[r0] : 0.f;
    float d1 = (r1 < NN) ? g_dinv[r1] : 0.f;
#pragma unroll
    for (int nt = 0; nt < 16; ++nt) {
        int col = nt * 8 + tig * 2;
        if (r0 < NN) {
            __nv_bfloat162 v = __floats2bfloat162_rn(d0 * c[nt][0], d0 * c[nt][1]);
            *(__nv_bfloat162*)(g_h1b + (size_t)r0 * 128 + col) = v;
        }
        if (r1 < NN) {
            __nv_bfloat162 v = __floats2bfloat162_rn(d1 * c[nt][2], d1 * c[nt][3]);
            *(__nv_bfloat162*)(g_h1b + (size_t)r1 * 128 + col) = v;
        }
    }
}

// ---------------- exclusive scan over g_deg -> g_ptr  (shuffle scan) ------
__global__ void k_scanA() {
    __shared__ int wsum[32];
    int b = blockIdx.x, t = threadIdx.x;
    int lane = t & 31, wid = t >> 5;
    int base = b * 4096 + t * 4;
    int v[4]; int s = 0;
#pragma unroll
    for (int j = 0; j < 4; ++j) {
        v[j] = (base + j < NN) ? g_deg[base + j] : 0;
        s += v[j];
    }
    int inc = s;
#pragma unroll
    for (int off = 1; off < 32; off <<= 1) {
        int n = __shfl_up_sync(0xffffffffu, inc, off);
        if (lane >= off) inc += n;
    }
    if (lane == 31) wsum[wid] = inc;
    __syncthreads();
    if (wid == 0) {
        int w = wsum[lane];
        int wi = w;
#pragma unroll
        for (int off = 1; off < 32; off <<= 1) {
            int n = __shfl_up_sync(0xffffffffu, wi, off);
            if (lane >= off) wi += n;
        }
        wsum[lane] = wi - w;   // exclusive warp prefix
    }
    __syncthreads();
    int excl = inc - s + wsum[wid];
    if (t == 1023) g_bsum[b] = inc + wsum[31];
    int run = excl;
#pragma unroll
    for (int j = 0; j < 4; ++j) {
        if (base + j < NN) g_ptr[base + j] = run;
        run += v[j];
    }
}

__global__ void k_scanSpine() {
    if (threadIdx.x == 0) {
        int acc = 0;
        for (int b = 0; b < 25; ++b) { int x = g_bsum[b]; g_bsum[b] = acc; acc += x; }
        g_ptr[NN] = acc;
    }
}

__global__ void k_scanAdd() {
    int i = blockIdx.x * blockDim.x + threadIdx.x;
    if (i < NN) g_ptr[i] += g_bsum[i / 4096];
}

// ---------------- CSR fill (index only; norm factored out) ----------------
__global__ void k_fill(const int* __restrict__ ei) {
    int e = blockIdx.x * blockDim.x + threadIdx.x;
    if (e >= NE) return;
    int r = ei[e];
    int c = ei[NE + e];
    int pos = g_ptr[c] + atomicAdd(&g_fill[c], 1);
    g_srcs[pos] = r;
}

// ------- layer-1 aggregation (bf16 gathers) FUSED with skinny GEMM2 -------
__global__ void k_agg1h2(const float* __restrict__ b1,
                         const float* __restrict__ W2) {
    int warp = (blockIdx.x * blockDim.x + threadIdx.x) >> 5;
    int lane = threadIdx.x & 31;
    if (warp >= NN) return;
    int p0 = g_ptr[warp], p1 = g_ptr[warp + 1];
    float d = g_dinv[warp];

    float ax, ay, az, aw;
    {   // self row (pre-scaled, bf16)
        uint2 raw = *(const uint2*)(g_h1b + (size_t)warp * 128 + lane * 4);
        float2 f0 = __bfloat1622float2(*reinterpret_cast<__nv_bfloat162*>(&raw.x));
        float2 f1 = __bfloat1622float2(*reinterpret_cast<__nv_bfloat162*>(&raw.y));
        ax = f0.x; ay = f0.y; az = f1.x; aw = f1.y;
    }
    for (int e = p0; e < p1; ++e) {
        int r = g_srcs[e];
        uint2 raw = *(const uint2*)(g_h1b + (size_t)r * 128 + lane * 4);
        float2 f0 = __bfloat1622float2(*reinterpret_cast<__nv_bfloat162*>(&raw.x));
        float2 f1 = __bfloat1622float2(*reinterpret_cast<__nv_bfloat162*>(&raw.y));
        ax += f0.x; ay += f0.y; az += f1.x; aw += f1.y;
    }
    float4 bb = ((const float4*)b1)[lane];
    ax = fmaxf(fmaf(d, ax, bb.x), 0.f);
    ay = fmaxf(fmaf(d, ay, bb.y), 0.f);
    az = fmaxf(fmaf(d, az, bb.z), 0.f);
    aw = fmaxf(fmaf(d, aw, bb.w), 0.f);

    const float4* w2p = (const float4*)(W2 + lane * 8);
    float4 wA = w2p[0];
    float4 wB = w2p[1];
    float s0 = ax * wA.x + ay * wA.z + az * wB.x + aw * wB.z;
    float s1 = ax * wA.y + ay * wA.w + az * wB.y + aw * wB.w;
#pragma unroll
    for (int off = 16; off > 0; off >>= 1) {
        s0 += __shfl_xor_sync(0xffffffffu, s0, off);
        s1 += __shfl_xor_sync(0xffffffffu, s1, off);
    }
    if (lane == 0) {
        g_h2[warp * 2 + 0] = d * s0;
        g_h2[warp * 2 + 1] = d * s1;
    }
}

// ---------------- layer-2 aggregation + mean-pool partial -----------------
__global__ void k_agg2pool(const float* __restrict__ b2,
                           const int* __restrict__ batch) {
    __shared__ float s_sums[NG * NC];
    __shared__ float s_cnt[NG];
    int t = threadIdx.x;
    if (t < NG * NC) s_sums[t] = 0.f;
    if (t < NG) s_cnt[t] = 0.f;
    __syncthreads();

    int i = blockIdx.x * blockDim.x + t;
    if (i < NN) {
        float d = g_dinv[i];
        float a0 = g_h2[i * 2 + 0];
        float a1 = g_h2[i * 2 + 1];
        int p0 = g_ptr[i], p1 = g_ptr[i + 1];
        for (int e = p0; e < p1; ++e) {
            int r = g_srcs[e];
            a0 += g_h2[r * 2 + 0];
            a1 += g_h2[r * 2 + 1];
        }
        a0 = fmaf(d, a0, b2[0]);
        a1 = fmaf(d, a1, b2[1]);
        int g = batch[i];
        atomicAdd(&s_sums[g * 2 + 0], a0);
        atomicAdd(&s_sums[g * 2 + 1], a1);
        atomicAdd(&s_cnt[g], 1.f);
    }
    __syncthreads();
    if (t < NG * NC) atomicAdd(&g_sums[t], s_sums[t]);
    if (t < NG) atomicAdd(&g_cnts[t], s_cnt[t]);
}

// ---------------- final: mean + log_softmax -------------------------------
__global__ void k_final(float* __restrict__ out) {
    int t = threadIdx.x;
    if (t >= NG) return;
    float c = fmaxf(g_cnts[t], 1.f);
    float p0 = g_sums[t * 2 + 0] / c;
    float p1 = g_sums[t * 2 + 1] / c;
    float m = fmaxf(p0, p1);
    float l = m + logf(expf(p0 - m) + expf(p1 - m));
    out[t * 2 + 0] = p0 - l;
    out[t * 2 + 1] = p1 - l;
}

// ---------------- launch --------------------------------------------------
extern "C" void kernel_launch(void* const* d_in, const int* in_sizes, int n_in,
                              void* d_out, int out_size) {
    const float* x     = (const float*)d_in[0];
    const int*   ei    = (const int*)d_in[1];     // int32 (JAX x64 disabled)
    const int*   batch = (const int*)d_in[2];
    const float* W1    = (const float*)d_in[3];
    const float* b1    = (const float*)d_in[4];
    const float* W2    = (const float*)d_in[5];
    const float* b2    = (const float*)d_in[6];
    float* out = (float*)d_out;

    k_reset<<<(NN + 255) / 256, 256>>>(W1);       // also builds g_wfrag
    k_hist<<<(NE + 255) / 256, 256>>>(ei);
    k_dinv<<<(NN + 255) / 256, 256>>>();
    k_gemm1<<<(NN + 127) / 128, 256>>>(x);        // 4th launch -> ncu capture slot
    k_scanA<<<25, 1024>>>();
    k_scanSpine<<<1, 32>>>();
    k_scanAdd<<<(NN + 255) / 256, 256>>>();
    k_fill<<<(NE + 255) / 256, 256>>>(ei);
    k_agg1h2<<<(NN * 32 + 255) / 256, 256>>>(b1, W2);
    k_agg2pool<<<(NN + 255) / 256, 256>>>(b2, batch);
    k_final<<<1, 32>>>(out);
}

// round 8
// speedup vs baseline: 1.9647x; 1.0135x over previous
#include <cuda_runtime.h>
#include <cuda_bf16.h>
#include <math.h>

#define NN 100000
#define NE 800000
#define NG 16
#define NF 128
#define NH 128
#define NC 2

#define GB 782            // gemm blocks in k_gemmfill
#define FB 3125           // fill blocks  ((NE+255)/256)
#define HB 3125           // hist blocks

// ---------------- persistent scratch (alloc-free rule: __device__ globals) ---
// NOTE: zeroed at module load; k_finalclean re-zeroes deg/fill/sums/cnts at the
// end of every call, so each invocation starts from the same state.
__device__ int            g_deg[NN];
__device__ float          g_dinv[NN];
__device__ int            g_ptr[NN + 1];
__device__ int            g_fill[NN];
__device__ int            g_srcs[NE];
__device__ __nv_bfloat16  g_h1b[(size_t)NN * NF];  // bf16(x @ W1)  (UNscaled)
__device__ float          g_h2[NN * NC];           // dinv * (act @ W2)
__device__ float          g_sums[NG * NC];
__device__ float          g_cnts[NG];
__device__ int            g_bsum[32];
__device__ float4         g_wfrag[16 * 8 * 32];    // W1 in tf32 mma-fragment order

// ---------------- helpers -------------------------------------------------
__device__ __forceinline__ unsigned f2tf32(float x) {
    unsigned r;
    asm("cvt.rna.tf32.f32 %0, %1;" : "=r"(r) : "f"(x));
    return r;
}

__device__ __forceinline__ void mma_tf32(float& c0, float& c1, float& c2, float& c3,
                                         unsigned a0, unsigned a1, unsigned a2, unsigned a3,
                                         unsigned b0, unsigned b1) {
    asm("mma.sync.aligned.m16n8k8.row.col.f32.tf32.tf32.f32 "
        "{%0,%1,%2,%3}, {%4,%5,%6,%7}, {%8,%9}, {%0,%1,%2,%3};"
        : "+f"(c0), "+f"(c1), "+f"(c2), "+f"(c3)
        : "r"(a0), "r"(a1), "r"(a2), "r"(a3), "r"(b0), "r"(b1));
}

// ---------- launch 1: degree histogram  ||  W1 fragment transform ---------
__global__ void k_histinit(const int* __restrict__ ei, const float* __restrict__ W) {
    int b = blockIdx.x;
    if (b < HB) {
        int e = b * 256 + threadIdx.x;
        if (e < NE) atomicAdd(&g_deg[ei[NE + e]], 1);
    } else {
        int i = (b - HB) * 256 + threadIdx.x;       // 0..4095
        int lane = i & 31, ntp = (i >> 5) & 7, kg = i >> 8;
        int g = lane >> 2, tig = lane & 3;
        int klo = kg * 8 + tig, khi = klo + 4;
        int n0 = ntp * 16 + g, n1 = n0 + 8;
        float4 f;
        f.x = __uint_as_float(f2tf32(W[klo * 128 + n0]));
        f.y = __uint_as_float(f2tf32(W[khi * 128 + n0]));
        f.z = __uint_as_float(f2tf32(W[klo * 128 + n1]));
        f.w = __uint_as_float(f2tf32(W[khi * 128 + n1]));
        g_wfrag[i] = f;
    }
}

// ---------- launch 2: exclusive scan of deg -> ptr, plus dinv -------------
__global__ void k_scanA() {
    __shared__ int wsum[32];
    int b = blockIdx.x, t = threadIdx.x;
    int lane = t & 31, wid = t >> 5;
    int base = b * 4096 + t * 4;
    int v[4]; int s = 0;
#pragma unroll
    for (int j = 0; j < 4; ++j) {
        v[j] = (base + j < NN) ? g_deg[base + j] : 0;
        s += v[j];
    }
#pragma unroll
    for (int j = 0; j < 4; ++j)
        if (base + j < NN) g_dinv[base + j] = rsqrtf((float)(v[j] + 1));
    int inc = s;
#pragma unroll
    for (int off = 1; off < 32; off <<= 1) {
        int n = __shfl_up_sync(0xffffffffu, inc, off);
        if (lane >= off) inc += n;
    }
    if (lane == 31) wsum[wid] = inc;
    __syncthreads();
    if (wid == 0) {
        int w = wsum[lane];
        int wi = w;
#pragma unroll
        for (int off = 1; off < 32; off <<= 1) {
            int n = __shfl_up_sync(0xffffffffu, wi, off);
            if (lane >= off) wi += n;
        }
        wsum[lane] = wi - w;
    }
    __syncthreads();
    int excl = inc - s + wsum[wid];
    if (t == 1023) g_bsum[b] = inc + wsum[31];
    int run = excl;
#pragma unroll
    for (int j = 0; j < 4; ++j) {
        if (base + j < NN) g_ptr[base + j] = run;
        run += v[j];
    }
}

// ---------- launch 3: spine scan folded into the add pass -----------------
__global__ void k_spineAdd() {
    __shared__ int off[32];
    int t = threadIdx.x;
    if (t < 32) {
        int v = (t < 25) ? g_bsum[t] : 0;
        int inc = v;
#pragma unroll
        for (int o = 1; o < 32; o <<= 1) {
            int n = __shfl_up_sync(0xffffffffu, inc, o);
            if (t >= o) inc += n;
        }
        off[t] = inc - v;     // exclusive prefix of block sums
    }
    __syncthreads();
    int i = blockIdx.x * 1024 + t;
    if (i < NN) g_ptr[i] += off[i >> 12];
    if (i == 0) g_ptr[NN] = NE;
}

// ---------- launch 4 (ncu slot): GEMM1 blocks || CSR-fill blocks ----------
// gemm: g_h1b = bf16(X @ W1), tf32 MMA, frag-B from g_wfrag.
// fill: scatter source indices into CSR slots (independent of gemm).
__global__ __launch_bounds__(256) void k_gemmfill(const float* __restrict__ X,
                                                  const int* __restrict__ ei) {
    __shared__ float  As[128][36];
    __shared__ float4 Wfs[1024];

    if (blockIdx.x >= GB) {                 // ---- fill branch ----
        int e = (blockIdx.x - GB) * 256 + threadIdx.x;
        if (e < NE) {
            int r = ei[e];
            int c = ei[NE + e];
            int pos = g_ptr[c] + atomicAdd(&g_fill[c], 1);
            g_srcs[pos] = r;
        }
        return;
    }

    // ---- gemm branch ----
    int tid  = threadIdx.x;
    int warp = tid >> 5, lane = tid & 31;
    int g    = lane >> 2, tig = lane & 3;
    int bm   = blockIdx.x * 128;
    int wrow = warp * 16;

    float c[16][4];
#pragma unroll
    for (int nt = 0; nt < 16; ++nt)
#pragma unroll
        for (int j = 0; j < 4; ++j) c[nt][j] = 0.f;

    for (int k0 = 0; k0 < 128; k0 += 32) {
#pragma unroll
        for (int i = 0; i < 4; ++i) {
            int idx = tid + i * 256;
            int row = idx >> 3, c4 = (idx & 7) * 4;
            int grow = bm + row;
            float4 v = (grow < NN)
                ? *(const float4*)(X + (size_t)grow * 128 + k0 + c4)
                : make_float4(0.f, 0.f, 0.f, 0.f);
            float4 tv;
            tv.x = __uint_as_float(f2tf32(v.x));
            tv.y = __uint_as_float(f2tf32(v.y));
            tv.z = __uint_as_float(f2tf32(v.z));
            tv.w = __uint_as_float(f2tf32(v.w));
            *(float4*)&As[row][c4] = tv;     // row stride 144B keeps 16B align
        }
        {
            const float4* wsrc = g_wfrag + (k0 >> 3) * 256;
#pragma unroll
            for (int i = 0; i < 4; ++i) {
                int idx = tid + i * 256;
                Wfs[idx] = wsrc[idx];
            }
        }
        __syncthreads();
#pragma unroll
        for (int ks = 0; ks < 4; ++ks) {
            int kk = ks * 8;
            unsigned a0 = __float_as_uint(As[wrow + g    ][kk + tig    ]);
            unsigned a1 = __float_as_uint(As[wrow + g + 8][kk + tig    ]);
            unsigned a2 = __float_as_uint(As[wrow + g    ][kk + tig + 4]);
            unsigned a3 = __float_as_uint(As[wrow + g + 8][kk + tig + 4]);
            const float4* wp = &Wfs[ks * 256 + lane];
#pragma unroll
            for (int ntp = 0; ntp < 8; ++ntp) {
                float4 bf = wp[ntp * 32];
                mma_tf32(c[2 * ntp][0], c[2 * ntp][1], c[2 * ntp][2], c[2 * ntp][3],
                         a0, a1, a2, a3,
                         __float_as_uint(bf.x), __float_as_uint(bf.y));
                mma_tf32(c[2 * ntp + 1][0], c[2 * ntp + 1][1], c[2 * ntp + 1][2], c[2 * ntp + 1][3],
                         a0, a1, a2, a3,
                         __float_as_uint(bf.z), __float_as_uint(bf.w));
            }
        }
        __syncthreads();
    }

    // epilogue: store raw bf16 (dinv applied later in agg1h2)
    int r0 = bm + wrow + g;
    int r1 = r0 + 8;
#pragma unroll
    for (int nt = 0; nt < 16; ++nt) {
        int col = nt * 8 + tig * 2;
        if (r0 < NN) {
            __nv_bfloat162 v = __floats2bfloat162_rn(c[nt][0], c[nt][1]);
            *(__nv_bfloat162*)(g_h1b + (size_t)r0 * 128 + col) = v;
        }
        if (r1 < NN) {
            __nv_bfloat162 v = __floats2bfloat162_rn(c[nt][2], c[nt][3]);
            *(__nv_bfloat162*)(g_h1b + (size_t)r1 * 128 + col) = v;
        }
    }
}

// ---------- launch 5: layer-1 aggregation + skinny GEMM2 (warp/node) ------
__global__ void k_agg1h2(const float* __restrict__ b1,
                         const float* __restrict__ W2) {
    int warp = (blockIdx.x * blockDim.x + threadIdx.x) >> 5;
    int lane = threadIdx.x & 31;
    if (warp >= NN) return;
    int p0 = g_ptr[warp], p1 = g_ptr[warp + 1];
    float dc = g_dinv[warp];

    float ax, ay, az, aw;
    {   // self term: dc * row_i
        uint2 raw = *(const uint2*)(g_h1b + (size_t)warp * 128 + lane * 4);
        float2 f0 = __bfloat1622float2(*reinterpret_cast<__nv_bfloat162*>(&raw.x));
        float2 f1 = __bfloat1622float2(*reinterpret_cast<__nv_bfloat162*>(&raw.y));
        ax = dc * f0.x; ay = dc * f0.y; az = dc * f1.x; aw = dc * f1.y;
    }
    for (int e = p0; e < p1; ++e) {
        int r = g_srcs[e];
        float dr = g_dinv[r];
        uint2 raw = *(const uint2*)(g_h1b + (size_t)r * 128 + lane * 4);
        float2 f0 = __bfloat1622float2(*reinterpret_cast<__nv_bfloat162*>(&raw.x));
        float2 f1 = __bfloat1622float2(*reinterpret_cast<__nv_bfloat162*>(&raw.y));
        ax = fmaf(dr, f0.x, ax); ay = fmaf(dr, f0.y, ay);
        az = fmaf(dr, f1.x, az); aw = fmaf(dr, f1.y, aw);
    }
    float4 bb = ((const float4*)b1)[lane];
    ax = fmaxf(fmaf(dc, ax, bb.x), 0.f);
    ay = fmaxf(fmaf(dc, ay, bb.y), 0.f);
    az = fmaxf(fmaf(dc, az, bb.z), 0.f);
    aw = fmaxf(fmaf(dc, aw, bb.w), 0.f);

    const float4* w2p = (const float4*)(W2 + lane * 8);
    float4 wA = w2p[0];
    float4 wB = w2p[1];
    float s0 = ax * wA.x + ay * wA.z + az * wB.x + aw * wB.z;
    float s1 = ax * wA.y + ay * wA.w + az * wB.y + aw * wB.w;
#pragma unroll
    for (int off = 16; off > 0; off >>= 1) {
        s0 += __shfl_xor_sync(0xffffffffu, s0, off);
        s1 += __shfl_xor_sync(0xffffffffu, s1, off);
    }
    if (lane == 0) {
        g_h2[warp * 2 + 0] = dc * s0;   // pre-scaled for layer 2
        g_h2[warp * 2 + 1] = dc * s1;
    }
}

// ---------- launch 6: layer-2 aggregation + mean-pool partials ------------
__global__ void k_agg2pool(const float* __restrict__ b2,
                           const int* __restrict__ batch) {
    __shared__ float s_sums[NG * NC];
    __shared__ float s_cnt[NG];
    int t = threadIdx.x;
    if (t < NG * NC) s_sums[t] = 0.f;
    if (t < NG) s_cnt[t] = 0.f;
    __syncthreads();

    int i = blockIdx.x * blockDim.x + t;
    if (i < NN) {
        float d = g_dinv[i];
        float a0 = g_h2[i * 2 + 0];
        float a1 = g_h2[i * 2 + 1];
        int p0 = g_ptr[i], p1 = g_ptr[i + 1];
        for (int e = p0; e < p1; ++e) {
            int r = g_srcs[e];
            a0 += g_h2[r * 2 + 0];
            a1 += g_h2[r * 2 + 1];
        }
        a0 = fmaf(d, a0, b2[0]);
        a1 = fmaf(d, a1, b2[1]);
        int g = batch[i];
        atomicAdd(&s_sums[g * 2 + 0], a0);
        atomicAdd(&s_sums[g * 2 + 1], a1);
        atomicAdd(&s_cnt[g], 1.f);
    }
    __syncthreads();
    if (t < NG * NC) atomicAdd(&g_sums[t], s_sums[t]);
    if (t < NG) atomicAdd(&g_cnts[t], s_cnt[t]);
}

// ---------- launch 7: log_softmax + state re-zero for next invocation -----
__global__ void k_finalclean(float* __restrict__ out) {
    int i = blockIdx.x * blockDim.x + threadIdx.x;
    if (i < NN) { g_deg[i] = 0; g_fill[i] = 0; }
    if (blockIdx.x == 0) {
        int t = threadIdx.x;
        if (t < NG) {
            float c = fmaxf(g_cnts[t], 1.f);
            float p0 = g_sums[t * 2 + 0] / c;
            float p1 = g_sums[t * 2 + 1] / c;
            float m = fmaxf(p0, p1);
            float l = m + logf(expf(p0 - m) + expf(p1 - m));
            out[t * 2 + 0] = p0 - l;
            out[t * 2 + 1] = p1 - l;
            g_sums[t * 2 + 0] = 0.f;   // re-zero after reading (block-0 only)
            g_sums[t * 2 + 1] = 0.f;
            g_cnts[t] = 0.f;
        }
    }
}

// ---------------- launch --------------------------------------------------
extern "C" void kernel_launch(void* const* d_in, const int* in_sizes, int n_in,
                              void* d_out, int out_size) {
    const float* x     = (const float*)d_in[0];
    const int*   ei    = (const int*)d_in[1];     // int32 (JAX x64 disabled)
    const int*   batch = (const int*)d_in[2];
    const float* W1    = (const float*)d_in[3];
    const float* b1    = (const float*)d_in[4];
    const float* W2    = (const float*)d_in[5];
    const float* b2    = (const float*)d_in[6];
    float* out = (float*)d_out;

    k_histinit<<<HB + 16, 256>>>(ei, W1);
    k_scanA<<<25, 1024>>>();
    k_spineAdd<<<(NN + 1023) / 1024, 1024>>>();
    k_gemmfill<<<GB + FB, 256>>>(x, ei);          // 4th launch -> ncu slot
    k_agg1h2<<<(NN * 32 + 255) / 256, 256>>>(b1, W2);
    k_agg2pool<<<(NN + 255) / 256, 256>>>(b2, batch);
    k_finalclean<<<(NN + 255) / 256, 256>>>(out);
}